// round 3
// baseline (speedup 1.0000x reference)
#include <cuda_runtime.h>
#include <stdint.h>

#define T_ 1024
#define B_ 64
#define H_ 256
#define G3 768   // 3*H

typedef unsigned long long ull;

// ---------------- scratch (static device globals; no runtime allocation) ----------------
__device__ float g_xg[(size_t)2 * T_ * G3 * B_];   // [dir][t][n=gate*H+j][b]  (~402 MB)
__device__ float g_y [(size_t)2 * T_ * H_ * B_];   // [dir][t][j][b]           (~128 MB)

// f32x2 packed math helpers
__device__ __forceinline__ void fma2(ull& acc, ull a, ull b) {
    asm("fma.rn.f32x2 %0, %1, %2, %0;" : "+l"(acc) : "l"(a), "l"(b));
}
__device__ __forceinline__ ull add2(ull a, ull b) {
    ull r; asm("add.rn.f32x2 %0, %1, %2;" : "=l"(r) : "l"(a), "l"(b)); return r;
}
__device__ __forceinline__ ull dup32(float v) {
    ull r; unsigned u = __float_as_uint(v);
    asm("mov.b64 %0, {%1, %1};" : "=l"(r) : "r"(u));
    return r;
}
__device__ __forceinline__ float2 u2f(ull v) {
    float2 f;
    f.x = __uint_as_float((unsigned)v);
    f.y = __uint_as_float((unsigned)(v >> 32));
    return f;
}
__device__ __forceinline__ uint32_t smem_u32(const void* p) {
    uint32_t a;
    asm("{ .reg .u64 t; cvta.to.shared.u64 t, %1; cvt.u32.u64 %0, t; }" : "=r"(a) : "l"(p));
    return a;
}
__device__ __forceinline__ uint32_t mapa_u32(uint32_t saddr, uint32_t rank) {
    uint32_t r;
    asm("mapa.shared::cluster.u32 %0, %1, %2;" : "=r"(r) : "r"(saddr), "r"(rank));
    return r;
}
__device__ __forceinline__ void st_cluster_b64(uint32_t addr, ull v) {
    asm volatile("st.shared::cluster.b64 [%0], %1;" :: "r"(addr), "l"(v) : "memory");
}
__device__ __forceinline__ void cluster_sync_() {
    asm volatile("barrier.cluster.arrive.aligned;" ::: "memory");
    asm volatile("barrier.cluster.wait.aligned;" ::: "memory");
}

// ---------------- phase 1: xg = gather(emb) @ W_ih^T + b_ih, stored transposed [t][n][b] --
__global__ void __launch_bounds__(256) gemm_xg(const int* __restrict__ seq,
                                               const float* __restrict__ emb,
                                               const float* __restrict__ Wf,
                                               const float* __restrict__ Wb,
                                               const float* __restrict__ bf,
                                               const float* __restrict__ bb,
                                               const int* __restrict__ lengths) {
    int id = blockIdx.x;
    int t   = id / 24;
    int r   = id % 24;
    int bt  = r & 1;               // b half-tile
    int nt2 = r >> 1;              // 0..11
    int d   = nt2 / 6;
    int n_base = (nt2 % 6) * 128;

    if (t >= __ldg(&lengths[bt * 32])) return;   // fully-masked tile

    const float* W    = d ? Wb : Wf;
    const float* bias = d ? bb : bf;

    __shared__ float  eT[32][40];
    __shared__ float2 wd2[32 * 128];
    __shared__ int    tok[32];

    int tid = threadIdx.x;
    if (tid < 32) tok[tid] = seq[t * 64 + bt * 32 + tid];

    int nq = tid >> 3, bq = tid & 7;
    int n0 = nq * 4, b0 = bq * 4;

    ull acc[4][2];
#pragma unroll
    for (int i = 0; i < 4; i++) { acc[i][0] = 0ull; acc[i][1] = 0ull; }

    const float4* emb4 = reinterpret_cast<const float4*>(emb);
    const float4* W4   = reinterpret_cast<const float4*>(W);

    for (int k0 = 0; k0 < 256; k0 += 32) {
        __syncthreads();
        {
            int b = tid >> 3, kq = tid & 7;
            float4 v = emb4[(size_t)tok[b] * 64 + (k0 >> 2) + kq];
            eT[kq * 4 + 0][b] = v.x; eT[kq * 4 + 1][b] = v.y;
            eT[kq * 4 + 2][b] = v.z; eT[kq * 4 + 3][b] = v.w;
        }
#pragma unroll
        for (int l = 0; l < 4; l++) {
            int fid = tid + l * 256;
            int n = fid >> 3, kq = fid & 7;
            float4 v = W4[(size_t)(n_base + n) * 64 + (k0 >> 2) + kq];
            wd2[(kq * 4 + 0) * 128 + n] = make_float2(v.x, v.x);
            wd2[(kq * 4 + 1) * 128 + n] = make_float2(v.y, v.y);
            wd2[(kq * 4 + 2) * 128 + n] = make_float2(v.z, v.z);
            wd2[(kq * 4 + 3) * 128 + n] = make_float2(v.w, v.w);
        }
        __syncthreads();
#pragma unroll 8
        for (int kk = 0; kk < 32; kk++) {
            ulonglong2 hh = *reinterpret_cast<const ulonglong2*>(&eT[kk][b0]);
            ulonglong2 w01 = *reinterpret_cast<const ulonglong2*>(&wd2[kk * 128 + n0]);
            ulonglong2 w23 = *reinterpret_cast<const ulonglong2*>(&wd2[kk * 128 + n0 + 2]);
            fma2(acc[0][0], hh.x, w01.x); fma2(acc[0][1], hh.y, w01.x);
            fma2(acc[1][0], hh.x, w01.y); fma2(acc[1][1], hh.y, w01.y);
            fma2(acc[2][0], hh.x, w23.x); fma2(acc[2][1], hh.y, w23.x);
            fma2(acc[3][0], hh.x, w23.y); fma2(acc[3][1], hh.y, w23.y);
        }
    }

    float* out = &g_xg[(size_t)d * T_ * G3 * B_ + (size_t)t * G3 * B_];
#pragma unroll
    for (int i = 0; i < 4; i++) {
        int n = n_base + n0 + i;
        float bv = bias[n];
        float2 lo = u2f(acc[i][0]), hi = u2f(acc[i][1]);
        float4 v;
        v.x = lo.x + bv; v.y = lo.y + bv; v.z = hi.x + bv; v.w = hi.y + bv;
        *reinterpret_cast<float4*>(&out[(size_t)n * 64 + bt * 32 + b0]) = v;
    }
}

// ---------------- phase 2: clustered bidirectional GRU recurrence (no global barrier) ----
// 16 clusters x 8 CTAs.  Cluster -> (dir, 8 batches).  CTA rank r -> 32 hidden units.
// h exchanged through DSMEM each step; one cluster.sync per step.
// Threads: 256 = kh(4 k-quarters) x [jp(16 j-pairs) x bp(4 batch-pairs)].
__global__ void __launch_bounds__(256) __cluster_dims__(8, 1, 1)
recur_kernel(const float* __restrict__ Whh_f,
             const float* __restrict__ Whh_b,
             const float* __restrict__ bhh_f,
             const float* __restrict__ bhh_b,
             const int* __restrict__ lengths,
             float* __restrict__ out) {
    extern __shared__ char smraw[];
    float* wpack = reinterpret_cast<float*>(smraw);              // [256][16][8] 128 KB (6 used/8)
    float* hbuf  = reinterpret_cast<float*>(smraw + 131072);     // [2][256][8]  16 KB
    ull*   spart = reinterpret_cast<ull*>(smraw + 131072 + 16384); // [3][64][6]  9 KB

    int bid = blockIdx.x;
    int d  = bid >> 6;           // direction
    int cb = (bid >> 3) & 7;     // batch-group within dir
    int r  = bid & 7;            // cluster rank -> j slice
    const float* Whh = d ? Whh_b : Whh_f;
    const float* bhh = d ? bhh_b : bhh_f;

    int tid = threadIdx.x;
    int kh = tid >> 6;                         // 0..3
    int t6 = tid & 63;
    int jp = ((t6 >> 5) << 3) | (t6 & 7);      // 0..15 (warp = 8 jp x 4 bp)
    int bp = (t6 >> 3) & 3;                    // 0..3
    int j0 = r * 32 + jp * 2;
    int b0 = cb * 8 + bp * 2;                  // global batch

    // W slice: wpack[k][jp][e], e = gate*2+jj : (r0,r1,z0,z1,n0,n1,-,-)
    for (int idx = tid; idx < 256 * 16 * 6; idx += 256) {
        int k = idx / 96;
        int rem = idx - k * 96;
        int jp2 = rem / 6;
        int e = rem - jp2 * 6;
        int gate = e >> 1, jj = e & 1;
        wpack[(k * 16 + jp2) * 8 + e] =
            Whh[(size_t)(gate * 256 + r * 32 + jp2 * 2 + jj) * 256 + k];
    }
    for (int idx = tid; idx < 2 * 256 * 8; idx += 256) hbuf[idx] = 0.f;

    float br0 = bhh[0 * 256 + j0], br1 = bhh[0 * 256 + j0 + 1];
    float bz0 = bhh[1 * 256 + j0], bz1 = bhh[1 * 256 + j0 + 1];
    float bn0 = bhh[2 * 256 + j0], bn1 = bhh[2 * 256 + j0 + 1];
    int len0 = lengths[b0], len1 = lengths[b0 + 1];

    uint32_t hbuf_addr = smem_u32(smraw) + 131072;
    const float* xgbase = &g_xg[(size_t)d * T_ * G3 * B_];
    float* yout = &g_y[(size_t)d * T_ * H_ * B_];
    const int kb = kh * 64;

    cluster_sync_();   // W + zeroed hbuf ready cluster-wide

    for (int step = 0; step < T_; step++) {
        int t = d ? (T_ - 1 - step) : step;
        int p = step & 1;
        const float* hrd = &hbuf[p * 2048];

        // prefetch xg for this step (only kh0 consumes)
        float2 xr0, xz0, xn0, xr1, xz1, xn1;
        if (kh == 0) {
            const float* xg = &xgbase[(size_t)t * G3 * B_];
            xr0 = __ldcs(reinterpret_cast<const float2*>(&xg[(size_t)(0 * 256 + j0) * 64 + b0]));
            xz0 = __ldcs(reinterpret_cast<const float2*>(&xg[(size_t)(1 * 256 + j0) * 64 + b0]));
            xn0 = __ldcs(reinterpret_cast<const float2*>(&xg[(size_t)(2 * 256 + j0) * 64 + b0]));
            xr1 = __ldcs(reinterpret_cast<const float2*>(&xg[(size_t)(0 * 256 + j0 + 1) * 64 + b0]));
            xz1 = __ldcs(reinterpret_cast<const float2*>(&xg[(size_t)(1 * 256 + j0 + 1) * 64 + b0]));
            xn1 = __ldcs(reinterpret_cast<const float2*>(&xg[(size_t)(2 * 256 + j0 + 1) * 64 + b0]));
        }

        // quarter-k dot products: acc[b][gate], each f32x2 over (j0, j0+1)
        ull a0r = 0, a0z = 0, a0n = 0, a1r = 0, a1z = 0, a1n = 0;
#pragma unroll 8
        for (int k = 0; k < 64; k++) {
            int kk = kb + k;
            float2 h2 = *reinterpret_cast<const float2*>(&hrd[kk * 8 + bp * 2]);
            ull hb0 = dup32(h2.x);
            ull hb1 = dup32(h2.y);
            const ull* wp = reinterpret_cast<const ull*>(&wpack[(kk * 16 + jp) * 8]);
            ull wr = wp[0], wz = wp[1], wn = wp[2];
            fma2(a0r, hb0, wr); fma2(a1r, hb1, wr);
            fma2(a0z, hb0, wz); fma2(a1z, hb1, wz);
            fma2(a0n, hb0, wn); fma2(a1n, hb1, wn);
        }

        if (kh) {
            ull* sp = &spart[((kh - 1) * 64 + t6) * 6];
            sp[0] = a0r; sp[1] = a0z; sp[2] = a0n;
            sp[3] = a1r; sp[4] = a1z; sp[5] = a1n;
        }
        __syncthreads();

        if (kh == 0) {
#pragma unroll
            for (int q = 0; q < 3; q++) {
                const ull* sp = &spart[(q * 64 + t6) * 6];
                a0r = add2(a0r, sp[0]); a0z = add2(a0z, sp[1]); a0n = add2(a0n, sp[2]);
                a1r = add2(a1r, sp[3]); a1z = add2(a1z, sp[4]); a1n = add2(a1n, sp[5]);
            }
            float2 f0r = u2f(a0r), f0z = u2f(a0z), f0n = u2f(a0n);
            float2 f1r = u2f(a1r), f1z = u2f(a1z), f1n = u2f(a1n);
            // hprev for (j0,j0+1) x (b0,b0+1)
            float2 hp_j0 = *reinterpret_cast<const float2*>(&hrd[j0 * 8 + bp * 2]);
            float2 hp_j1 = *reinterpret_cast<const float2*>(&hrd[(j0 + 1) * 8 + bp * 2]);

            float hn[2][2], yv[2][2];   // [jj][bb]
            bool m0 = (t < len0), m1 = (t < len1);
#pragma unroll
            for (int jj = 0; jj < 2; jj++) {
#pragma unroll
                for (int bb = 0; bb < 2; bb++) {
                    float ar = bb ? (jj ? f1r.y : f1r.x) : (jj ? f0r.y : f0r.x);
                    float az = bb ? (jj ? f1z.y : f1z.x) : (jj ? f0z.y : f0z.x);
                    float an = bb ? (jj ? f1n.y : f1n.x) : (jj ? f0n.y : f0n.x);
                    float xr = jj ? (bb ? xr1.y : xr1.x) : (bb ? xr0.y : xr0.x);
                    float xz = jj ? (bb ? xz1.y : xz1.x) : (bb ? xz0.y : xz0.x);
                    float xn = jj ? (bb ? xn1.y : xn1.x) : (bb ? xn0.y : xn0.x);
                    float bR = jj ? br1 : br0, bZ = jj ? bz1 : bz0, bN = jj ? bn1 : bn0;
                    float hp = jj ? (bb ? hp_j1.y : hp_j1.x) : (bb ? hp_j0.y : hp_j0.x);
                    float rg = 1.f / (1.f + __expf(-(xr + ar + bR)));
                    float zg = 1.f / (1.f + __expf(-(xz + az + bZ)));
                    float ng = 2.f / (1.f + __expf(-2.f * (xn + rg * (an + bN)))) - 1.f;
                    float hv = ng + zg * (hp - ng);
                    bool m = bb ? m1 : m0;
                    hn[jj][bb] = m ? hv : hp;
                    yv[jj][bb] = m ? hv : 0.f;
                }
            }

            // broadcast h_new to all 8 cluster CTAs (incl. self) via DSMEM
            ull v_j0, v_j1;
            {
                float2 t0 = make_float2(hn[0][0], hn[0][1]);
                float2 t1 = make_float2(hn[1][0], hn[1][1]);
                v_j0 = *reinterpret_cast<ull*>(&t0);
                v_j1 = *reinterpret_cast<ull*>(&t1);
            }
            uint32_t dst = hbuf_addr + (uint32_t)(((p ^ 1) * 2048 + j0 * 8 + bp * 2) * 4);
#pragma unroll
            for (uint32_t q = 0; q < 8; q++) {
                uint32_t pa = mapa_u32(dst, q);
                st_cluster_b64(pa, v_j0);
                st_cluster_b64(pa + 32, v_j1);
            }

            // y outputs
            *reinterpret_cast<float2*>(&yout[((size_t)t * H_ + j0) * 64 + b0]) =
                make_float2(yv[0][0], yv[0][1]);
            *reinterpret_cast<float2*>(&yout[((size_t)t * H_ + j0 + 1) * 64 + b0]) =
                make_float2(yv[1][0], yv[1][1]);
        }

        cluster_sync_();   // release our DSMEM stores; acquire peers'
    }

    // final hidden h(T) lives in hbuf[0] (full 256 x 8 in every CTA).
    // Each CTA writes its own j-slice: out[T*B*H + (d*64+b)*256 + j]
    {
        int jloc = tid >> 3, b = tid & 7;
        int j = r * 32 + jloc;
        out[(size_t)T_ * B_ * H_ + ((size_t)d * 64 + cb * 8 + b) * 256 + j] =
            hbuf[j * 8 + b];
    }
}

// ---------------- phase 3: outputs = yf + yb (transpose to [t][b][j]) ----------------
__global__ void __launch_bounds__(256) epilogue_kernel(float* __restrict__ out) {
    __shared__ float s[128][65];
    int t = blockIdx.x;
    const float* yf = &g_y[(size_t)0 * T_ * H_ * B_ + (size_t)t * H_ * B_];
    const float* yb = &g_y[(size_t)1 * T_ * H_ * B_ + (size_t)t * H_ * B_];
    for (int half = 0; half < 2; half++) {
        int jofs = half * 128;
        for (int idx = threadIdx.x; idx < 128 * 64; idx += 256) {
            int j = idx >> 6, b = idx & 63;
            size_t o = (size_t)(jofs + j) * 64 + b;
            s[j][b] = yf[o] + yb[o];
        }
        __syncthreads();
        for (int idx = threadIdx.x; idx < 128 * 64; idx += 256) {
            int b = idx >> 7, j = idx & 127;
            out[((size_t)t * 64 + b) * 256 + jofs + j] = s[j][b];
        }
        __syncthreads();
    }
}

// ---------------- launcher ----------------
extern "C" void kernel_launch(void* const* d_in, const int* in_sizes, int n_in,
                              void* d_out, int out_size) {
    const int*   seq  = (const int*)  d_in[0];
    const int*   lens = (const int*)  d_in[1];
    const float* emb  = (const float*)d_in[2];
    const float* Wihf = (const float*)d_in[3];
    const float* Whhf = (const float*)d_in[4];
    const float* bihf = (const float*)d_in[5];
    const float* bhhf = (const float*)d_in[6];
    const float* Wihb = (const float*)d_in[7];
    const float* Whhb = (const float*)d_in[8];
    const float* bihb = (const float*)d_in[9];
    const float* bhhb = (const float*)d_in[10];
    float* out = (float*)d_out;

    const int smem_recur = 131072 + 16384 + 9216;   // W 128K + h 16K + partials 9K
    cudaFuncSetAttribute(recur_kernel, cudaFuncAttributeMaxDynamicSharedMemorySize, smem_recur);

    gemm_xg<<<T_ * 24, 256>>>(seq, emb, Wihf, Wihb, bihf, bihb, lens);
    recur_kernel<<<128, 256, smem_recur>>>(Whhf, Whhb, bhhf, bhhb, lens, out);
    epilogue_kernel<<<T_, 256>>>(out);
}

// round 4
// speedup vs baseline: 1.9408x; 1.9408x over previous
#include <cuda_runtime.h>
#include <stdint.h>

#define T_ 1024
#define B_ 64
#define H_ 256
#define G3 768   // 3*H

typedef unsigned long long ull;

// ---------------- scratch (static device globals; no runtime allocation) ----------------
__device__ float g_xg[(size_t)2 * T_ * G3 * B_];   // [dir][t][n=gate*H+j][b]  (~402 MB)
__device__ float g_y [(size_t)2 * T_ * H_ * B_];   // [dir][t][j][b]           (~128 MB)
__device__ float g_h [2 * 2 * 8 * 8 * H_];         // [dir][parity][bg][b(8)][k(256)] 256 KB
__device__ unsigned g_cnt[16 * 32];                // one counter per (dir,bg), 128B apart

// f32x2 packed math helpers
__device__ __forceinline__ void fma2(ull& acc, ull a, ull b) {
    asm("fma.rn.f32x2 %0, %1, %2, %0;" : "+l"(acc) : "l"(a), "l"(b));
}
__device__ __forceinline__ ull add2(ull a, ull b) {
    ull r; asm("add.rn.f32x2 %0, %1, %2;" : "=l"(r) : "l"(a), "l"(b)); return r;
}
__device__ __forceinline__ float2 u2f(ull v) {
    float2 f;
    f.x = __uint_as_float((unsigned)v);
    f.y = __uint_as_float((unsigned)(v >> 32));
    return f;
}
__device__ __forceinline__ void red_release(unsigned* p) {
    asm volatile("red.add.release.gpu.u32 [%0], %1;" :: "l"(p), "r"(1u) : "memory");
}
__device__ __forceinline__ unsigned ld_acquire(const unsigned* p) {
    unsigned v;
    asm volatile("ld.acquire.gpu.u32 %0, [%1];" : "=r"(v) : "l"(p) : "memory");
    return v;
}

// ---------------- init: zero h state + group counters (runs every replay) ----------------
__global__ void __launch_bounds__(256) init_kernel() {
    int i = blockIdx.x * 256 + threadIdx.x;
    if (i < 2 * 2 * 8 * 8 * H_) g_h[i] = 0.f;
    if (i < 16 * 32) g_cnt[i] = 0u;
}

// ---------------- phase 1: xg = gather(emb) @ W_ih^T + b_ih, stored transposed [t][n][b] --
__global__ void __launch_bounds__(256) gemm_xg(const int* __restrict__ seq,
                                               const float* __restrict__ emb,
                                               const float* __restrict__ Wf,
                                               const float* __restrict__ Wb,
                                               const float* __restrict__ bf,
                                               const float* __restrict__ bb,
                                               const int* __restrict__ lengths) {
    int id = blockIdx.x;
    int t   = id / 24;
    int r   = id % 24;
    int bt  = r & 1;               // b half-tile
    int nt2 = r >> 1;              // 0..11
    int d   = nt2 / 6;
    int n_base = (nt2 % 6) * 128;

    if (t >= __ldg(&lengths[bt * 32])) return;   // fully-masked tile

    const float* W    = d ? Wb : Wf;
    const float* bias = d ? bb : bf;

    __shared__ float  eT[32][40];
    __shared__ float2 wd2[32 * 128];
    __shared__ int    tok[32];

    int tid = threadIdx.x;
    if (tid < 32) tok[tid] = seq[t * 64 + bt * 32 + tid];

    int nq = tid >> 3, bq = tid & 7;
    int n0 = nq * 4, b0 = bq * 4;

    ull acc[4][2];
#pragma unroll
    for (int i = 0; i < 4; i++) { acc[i][0] = 0ull; acc[i][1] = 0ull; }

    const float4* emb4 = reinterpret_cast<const float4*>(emb);
    const float4* W4   = reinterpret_cast<const float4*>(W);

    for (int k0 = 0; k0 < 256; k0 += 32) {
        __syncthreads();
        {
            int b = tid >> 3, kq = tid & 7;
            float4 v = emb4[(size_t)tok[b] * 64 + (k0 >> 2) + kq];
            eT[kq * 4 + 0][b] = v.x; eT[kq * 4 + 1][b] = v.y;
            eT[kq * 4 + 2][b] = v.z; eT[kq * 4 + 3][b] = v.w;
        }
#pragma unroll
        for (int l = 0; l < 4; l++) {
            int fid = tid + l * 256;
            int n = fid >> 3, kq = fid & 7;
            float4 v = W4[(size_t)(n_base + n) * 64 + (k0 >> 2) + kq];
            wd2[(kq * 4 + 0) * 128 + n] = make_float2(v.x, v.x);
            wd2[(kq * 4 + 1) * 128 + n] = make_float2(v.y, v.y);
            wd2[(kq * 4 + 2) * 128 + n] = make_float2(v.z, v.z);
            wd2[(kq * 4 + 3) * 128 + n] = make_float2(v.w, v.w);
        }
        __syncthreads();
#pragma unroll 8
        for (int kk = 0; kk < 32; kk++) {
            ulonglong2 hh = *reinterpret_cast<const ulonglong2*>(&eT[kk][b0]);
            ulonglong2 w01 = *reinterpret_cast<const ulonglong2*>(&wd2[kk * 128 + n0]);
            ulonglong2 w23 = *reinterpret_cast<const ulonglong2*>(&wd2[kk * 128 + n0 + 2]);
            fma2(acc[0][0], hh.x, w01.x); fma2(acc[0][1], hh.y, w01.x);
            fma2(acc[1][0], hh.x, w01.y); fma2(acc[1][1], hh.y, w01.y);
            fma2(acc[2][0], hh.x, w23.x); fma2(acc[2][1], hh.y, w23.x);
            fma2(acc[3][0], hh.x, w23.y); fma2(acc[3][1], hh.y, w23.y);
        }
    }

    float* out = &g_xg[(size_t)d * T_ * G3 * B_ + (size_t)t * G3 * B_];
#pragma unroll
    for (int i = 0; i < 4; i++) {
        int n = n_base + n0 + i;
        float bv = bias[n];
        float2 lo = u2f(acc[i][0]), hi = u2f(acc[i][1]);
        float4 v;
        v.x = lo.x + bv; v.y = lo.y + bv; v.z = hi.x + bv; v.w = hi.y + bv;
        *reinterpret_cast<float4*>(&out[(size_t)n * 64 + bt * 32 + b0]) = v;
    }
}

// ---------------- phase 2: grouped bidirectional GRU recurrence ----------------
// 128 CTAs = dir(2) x bg(8 batch-groups of 8) x r(8 j-groups of 32).
// Coupled group = the 8 CTAs sharing (dir,bg); they exchange h through L2 with a
// per-group release/acquire counter barrier each step.
// Thread = (jl 0..31) x (bl 0..7): one hidden unit j, one batch b; f32x2 over k.
__global__ void __launch_bounds__(256)
recur_kernel(const float* __restrict__ Whh_f,
             const float* __restrict__ Whh_b,
             const float* __restrict__ bhh_f,
             const float* __restrict__ bhh_b,
             const int* __restrict__ lengths,
             float* __restrict__ out) {
    extern __shared__ float sm[];
    float* wsm = sm;                       // [3][32][260]  99840 B
    float* hsm = sm + 3 * 32 * 260;        // [8][260]       8320 B

    int bid = blockIdx.x;
    int d  = bid >> 6;
    int rm = bid & 63;
    int bg = rm >> 3;       // batch group 0..7
    int r  = rm & 7;        // j group 0..7
    const float* Whh = d ? Whh_b : Whh_f;
    const float* bhh = d ? bhh_b : bhh_f;

    int tid = threadIdx.x;
    int jl = tid >> 3;      // 0..31
    int bl = tid & 7;       // 0..7
    int j  = r * 32 + jl;
    int b  = bg * 8 + bl;

    // load W slice: wsm[gate][jl][k] (rows padded to 260 floats, conflict-free)
    {
        const float4* W4 = reinterpret_cast<const float4*>(Whh);
        for (int i = tid; i < 6144; i += 256) {
            int gate = i >> 11;
            int rem  = i & 2047;
            int jl2  = rem >> 6;
            int kq   = rem & 63;
            float4 v = W4[(size_t)(gate * 256 + r * 32 + jl2) * 64 + kq];
            *reinterpret_cast<float4*>(&wsm[(gate * 32 + jl2) * 260 + kq * 4]) = v;
        }
    }
    float br = bhh[0 * 256 + j];
    float bz = bhh[1 * 256 + j];
    float bn = bhh[2 * 256 + j];
    int len_b = lengths[b];

    unsigned* cnt = &g_cnt[(d * 8 + bg) * 32];
    const float* xgbase = &g_xg[(size_t)d * T_ * G3 * B_];
    float* yout = &g_y[(size_t)d * T_ * H_ * B_];

    const float* wrp = &wsm[(0 * 32 + jl) * 260];
    const float* wzp = &wsm[(1 * 32 + jl) * 260];
    const float* wnp = &wsm[(2 * 32 + jl) * 260];
    const float* hb  = &hsm[bl * 260];
    __syncthreads();

    for (int step = 0; step < T_; step++) {
        int t = d ? (T_ - 1 - step) : step;
        int p = step & 1;

        // prefetch xg (independent of h) BEFORE the barrier to hide DRAM latency
        const float* xg = &xgbase[(size_t)t * G3 * B_];
        float xr = __ldcs(&xg[(size_t)(0 * 256 + j) * 64 + b]);
        float xz = __ldcs(&xg[(size_t)(1 * 256 + j) * 64 + b]);
        float xn = __ldcs(&xg[(size_t)(2 * 256 + j) * 64 + b]);

        // group barrier: wait until all 8 CTAs finished step-1
        if (step && tid == 0) {
            unsigned tgt = 8u * (unsigned)step;
            while (ld_acquire(cnt) < tgt) { }
        }
        __syncthreads();

        // stage h[bg slice] (8 x 256) into smem from L2
        const float4* hin4 = reinterpret_cast<const float4*>(
            &g_h[(((d * 2 + p) * 8) + bg) * (8 * H_)]);
#pragma unroll
        for (int l = 0; l < 2; l++) {
            int i = tid + l * 256;
            int b2 = i >> 6, kq = i & 63;
            *reinterpret_cast<float4*>(&hsm[b2 * 260 + kq * 4]) = __ldcg(&hin4[i]);
        }
        __syncthreads();

        // dot products: f32x2 over k, 6 accumulator chains
        ull a0[3] = {0ull, 0ull, 0ull};
        ull a1[3] = {0ull, 0ull, 0ull};
#pragma unroll 8
        for (int kq = 0; kq < 64; kq++) {
            int k = kq * 4;
            ulonglong2 h2 = *reinterpret_cast<const ulonglong2*>(&hb[k]);
            ulonglong2 wr2 = *reinterpret_cast<const ulonglong2*>(&wrp[k]);
            ulonglong2 wz2 = *reinterpret_cast<const ulonglong2*>(&wzp[k]);
            ulonglong2 wn2 = *reinterpret_cast<const ulonglong2*>(&wnp[k]);
            fma2(a0[0], h2.x, wr2.x); fma2(a1[0], h2.y, wr2.y);
            fma2(a0[1], h2.x, wz2.x); fma2(a1[1], h2.y, wz2.y);
            fma2(a0[2], h2.x, wn2.x); fma2(a1[2], h2.y, wn2.y);
        }
        float2 fr = u2f(add2(a0[0], a1[0]));
        float2 fz = u2f(add2(a0[1], a1[1]));
        float2 fn = u2f(add2(a0[2], a1[2]));
        float ar = fr.x + fr.y, az = fz.x + fz.y, an = fn.x + fn.y;

        float hp = hb[j];   // h_prev[b][j]
        float rg = 1.f / (1.f + __expf(-(xr + ar + br)));
        float zg = 1.f / (1.f + __expf(-(xz + az + bz)));
        float ng = 2.f / (1.f + __expf(-2.f * (xn + rg * (an + bn)))) - 1.f;
        float hv = ng + zg * (hp - ng);
        bool m = (t < len_b);
        float hnext = m ? hv : hp;
        float yv    = m ? hv : 0.f;

        float* hout = &g_h[(((d * 2 + (p ^ 1)) * 8) + bg) * (8 * H_)];
        __stcg(&hout[bl * 256 + j], hnext);
        yout[((size_t)t * H_ + j) * 64 + b] = yv;

        if (step == T_ - 1) {
            out[(size_t)T_ * B_ * H_ + ((size_t)d * 64 + b) * 256 + j] = hnext;
        }

        __syncthreads();                 // all stores issued (block-visible)
        if (tid == 0) red_release(cnt);  // gpu-scope release (cumulative)
    }
}

// ---------------- phase 3: outputs = yf + yb (transpose to [t][b][j]) ----------------
__global__ void __launch_bounds__(256) epilogue_kernel(float* __restrict__ out) {
    __shared__ float s[128][65];
    int t = blockIdx.x;
    const float* yf = &g_y[(size_t)0 * T_ * H_ * B_ + (size_t)t * H_ * B_];
    const float* yb = &g_y[(size_t)1 * T_ * H_ * B_ + (size_t)t * H_ * B_];
    for (int half = 0; half < 2; half++) {
        int jofs = half * 128;
        for (int idx = threadIdx.x; idx < 128 * 64; idx += 256) {
            int j = idx >> 6, b = idx & 63;
            size_t o = (size_t)(jofs + j) * 64 + b;
            s[j][b] = yf[o] + yb[o];
        }
        __syncthreads();
        for (int idx = threadIdx.x; idx < 128 * 64; idx += 256) {
            int b = idx >> 7, j = idx & 127;
            out[((size_t)t * 64 + b) * 256 + jofs + j] = s[j][b];
        }
        __syncthreads();
    }
}

// ---------------- launcher ----------------
extern "C" void kernel_launch(void* const* d_in, const int* in_sizes, int n_in,
                              void* d_out, int out_size) {
    const int*   seq  = (const int*)  d_in[0];
    const int*   lens = (const int*)  d_in[1];
    const float* emb  = (const float*)d_in[2];
    const float* Wihf = (const float*)d_in[3];
    const float* Whhf = (const float*)d_in[4];
    const float* bihf = (const float*)d_in[5];
    const float* bhhf = (const float*)d_in[6];
    const float* Wihb = (const float*)d_in[7];
    const float* Whhb = (const float*)d_in[8];
    const float* bihb = (const float*)d_in[9];
    const float* bhhb = (const float*)d_in[10];
    float* out = (float*)d_out;

    const int smem_recur = (3 * 32 * 260 + 8 * 260) * 4;   // 108160 B
    cudaFuncSetAttribute(recur_kernel, cudaFuncAttributeMaxDynamicSharedMemorySize, smem_recur);

    init_kernel<<<256, 256>>>();
    gemm_xg<<<T_ * 24, 256>>>(seq, emb, Wihf, Wihb, bihf, bihb, lens);
    recur_kernel<<<128, 256, smem_recur>>>(Whhf, Whhb, bhhf, bhhb, lens, out);
    epilogue_kernel<<<T_, 256>>>(out);
}